// round 12
// baseline (speedup 1.0000x reference)
#include <cuda_runtime.h>
#include <cstdint>

// CategorySpecificLinear via mma.sync.m16n8k8 TF32 (base sm_103; tcgen05 is
// rejected by this bench's ptxas target).
//
// Round 12: CTA 256(M)x128(N), 512 threads, 16 warps (4Mx4N), warp tile 64x32.
// acc halves to 64 regs/thread -> no spills; latency hidden by 4 warps/SMSP
// instead of register pipelining. 4-stage cp.async, x4-unrolled main loop,
// mid-chunk barrier+ISSUE, cross-chunk ks0 fragment preload. fa double-
// buffered, fb single-buffered JIT.

#define A_STAGE  32768                 // 256 x 32 f32, 128B rows, XOR swizzle
#define B_STAGE  17408                 // 32 x 136 f32
#define B_REG    (4 * A_STAGE)         // 131072
#define SMEM_DYN (4 * A_STAGE + 4 * B_STAGE)   // 200704

static __device__ __forceinline__ uint32_t smem_u32(const void* p){
    uint32_t a;
    asm("{ .reg .u64 t; cvta.to.shared.u64 t, %1; cvt.u32.u64 %0, t; }" : "=r"(a) : "l"(p));
    return a;
}
static __device__ __forceinline__ void cp16(uint32_t dst, const void* src){
    asm volatile("cp.async.cg.shared.global [%0], [%1], 16;"
                 :: "r"(dst), "l"(src) : "memory");
}
static __device__ __forceinline__ uint32_t f2tf(uint32_t bits){
    uint32_t r;
    asm("cvt.rna.tf32.f32 %0, %1;" : "=r"(r) : "f"(__uint_as_float(bits)));
    return r;
}
static __device__ __forceinline__ void mma_tf32(float d[4],
                                                uint32_t a0, uint32_t a1,
                                                uint32_t a2, uint32_t a3,
                                                uint32_t b0, uint32_t b1){
    asm volatile(
        "mma.sync.aligned.m16n8k8.row.col.f32.tf32.tf32.f32 "
        "{%0,%1,%2,%3}, {%4,%5,%6,%7}, {%8,%9}, {%0,%1,%2,%3};"
        : "+f"(d[0]), "+f"(d[1]), "+f"(d[2]), "+f"(d[3])
        : "r"(a0), "r"(a1), "r"(a2), "r"(a3), "r"(b0), "r"(b1));
}
static __device__ __forceinline__ uint32_t lds32(const char* p){
    return *(const uint32_t*)p;
}

__global__ __launch_bounds__(512, 1)
void cslin_mma10_kernel(const float* __restrict__ x,
                        const int*   __restrict__ cat_ids,
                        const float* __restrict__ W,
                        const float* __restrict__ bias,
                        float*       __restrict__ y)
{
    constexpr int IDIM = 1024, ODIM = 1024, TDIM = 512;
    extern __shared__ char dsm[];

    const int tid  = threadIdx.x;        // 0..511
    const int wid  = tid >> 5;           // 0..15
    const int lane = tid & 31;
    const int la3  = lane & 3;
    const int lg   = lane >> 2;

    const int n0 = blockIdx.x * 128;
    const int m0 = blockIdx.y * 256;
    const int bb = blockIdx.z;
    const int cat = __ldg(cat_ids + bb);

    const float* xb = x + (size_t)bb  * TDIM * IDIM;
    const float* Wc = W + (size_t)cat * IDIM * ODIM;
    const float* bc = bias + (size_t)cat * ODIM;
    float*       yb = y + (size_t)bb  * TDIM * ODIM;

    // ---- cp.async geometry (512 threads) ----
    // A: 2048 granules/chunk -> 4 per thread: row (t>>3)+64i, gcol t&7
    const float* aSrc = xb + (size_t)(m0 + (tid >> 3)) * IDIM + ((tid & 7) << 2);
    const uint32_t aDst = smem_u32(dsm)
        + (uint32_t)((tid >> 3) * 128)
        + (uint32_t)((((tid & 7) << 4)) ^ ((((tid >> 3) & 7)) << 4));
    // B: 1024 granules/chunk -> 2 per thread: row t>>4, gcols (t&15), (t&15)+16
    const float* bSrc = Wc + (size_t)(tid >> 4) * ODIM + n0 + ((tid & 15) << 2);
    const uint32_t bDst = smem_u32(dsm) + B_REG
        + (uint32_t)((tid >> 4) * 544 + ((tid & 15) << 4));

#define ISSUE(KC, S)                                                          \
    do {                                                                      \
        const float* _as = aSrc + (KC);                                       \
        const uint32_t _ad = aDst + (uint32_t)((S) * A_STAGE);                \
        _Pragma("unroll")                                                     \
        for (int i = 0; i < 4; i++)                                           \
            cp16(_ad + (uint32_t)(i * 8192), _as + (size_t)(64 * i) * IDIM);  \
        const float* _bs = bSrc + (size_t)(KC) * ODIM;                        \
        const uint32_t _bd = bDst + (uint32_t)((S) * B_STAGE);                \
        cp16(_bd, _bs);                                                       \
        cp16(_bd + 256u, _bs + 64);                                           \
    } while (0)

    // ---- warp tile 64x32 ----
    const int wm = (wid & 3) * 64;          // 0/64/128/192
    const int wn = (wid >> 2) * 32;         // 0/32/64/96

    const uint32_t swzA = (uint32_t)(lg << 4);
    const uint32_t aInv = (uint32_t)((wm + lg) * 128);            // + i*2048 (+1024)
    const uint32_t bInv = (uint32_t)(la3 * 544 + (wn + lg) * 4);  // + j*32 (+2176)
    const uint32_t aK   = (uint32_t)(la3 * 4);

    float acc[4][4][4];
    #pragma unroll
    for (int i = 0; i < 4; i++)
        #pragma unroll
        for (int j = 0; j < 4; j++)
            #pragma unroll
            for (int q = 0; q < 4; q++) acc[i][j][q] = 0.f;

    uint32_t fa0[16], fa1[16], fb[8];

#define LOAD_FA(FA, SA, KS)                                                   \
    do {                                                                      \
        const uint32_t _c0 = ((uint32_t)((KS) * 32) + aK) ^ swzA;             \
        const char* _pa0 = (SA) + (aInv + _c0);                               \
        const char* _pa1 = (SA) + (aInv + (_c0 ^ 16u));                       \
        _Pragma("unroll")                                                     \
        for (int i = 0; i < 4; i++){                                          \
            FA[4*i]   = f2tf(lds32(_pa0 + i * 2048));                         \
            FA[4*i+1] = f2tf(lds32(_pa0 + i * 2048 + 1024));                  \
            FA[4*i+2] = f2tf(lds32(_pa1 + i * 2048));                         \
            FA[4*i+3] = f2tf(lds32(_pa1 + i * 2048 + 1024));                  \
        }                                                                     \
    } while (0)

#define LOAD_FB(SB, KS)                                                       \
    do {                                                                      \
        const char* _pb = (SB) + (bInv + (KS) * 4352);                        \
        _Pragma("unroll")                                                     \
        for (int j = 0; j < 4; j++){                                          \
            fb[2*j]   = f2tf(lds32(_pb + j * 32));                            \
            fb[2*j+1] = f2tf(lds32(_pb + j * 32 + 2176));                     \
        }                                                                     \
    } while (0)

#define MMA_BLOCK(FA)                                                         \
    do {                                                                      \
        _Pragma("unroll")                                                     \
        for (int i = 0; i < 4; i++)                                           \
            _Pragma("unroll")                                                 \
            for (int j = 0; j < 4; j++)                                       \
                mma_tf32(acc[i][j], FA[4*i], FA[4*i+1], FA[4*i+2], FA[4*i+3], \
                         fb[2*j], fb[2*j+1]);                                 \
    } while (0)

    // One chunk; S compile-time. fa double-buffered, fb JIT per k-step.
#define CHUNK_BODY(C, S)                                                      \
    do {                                                                      \
        const char* sA = dsm + (S) * A_STAGE;                                 \
        const char* sB = dsm + B_REG + (S) * B_STAGE;                         \
        LOAD_FA(fa1, sA, 1);                                                  \
        MMA_BLOCK(fa0);            /* ks0, fb=ks0 */                          \
        LOAD_FB(sB, 1);                                                       \
        LOAD_FA(fa0, sA, 2);                                                  \
        MMA_BLOCK(fa1);            /* ks1 */                                  \
        LOAD_FB(sB, 2);                                                       \
        LOAD_FA(fa1, sA, 3);                                                  \
        MMA_BLOCK(fa0);            /* ks2 */                                  \
        LOAD_FB(sB, 3);                                                       \
        if ((C) + 3 < 32){                                                    \
            asm volatile("cp.async.wait_group 1;" ::: "memory");              \
            __syncthreads();                                                  \
            ISSUE(((C) + 3) * 32, ((S) + 3) & 3);                             \
            asm volatile("cp.async.commit_group;" ::: "memory");              \
        } else {                                                              \
            asm volatile("cp.async.wait_group 0;" ::: "memory");              \
            __syncthreads();                                                  \
        }                                                                     \
        MMA_BLOCK(fa1);            /* ks3 */                                  \
        if ((C) + 1 < 32){                                                    \
            const char* nA = dsm + (((S) + 1) & 3) * A_STAGE;                 \
            const char* nB = dsm + B_REG + (((S) + 1) & 3) * B_STAGE;         \
            LOAD_FA(fa0, nA, 0);                                              \
            LOAD_FB(nB, 0);                                                   \
        }                                                                     \
    } while (0)

    // ---- prologue: issue chunks 0..2, preload chunk 0 ks0 ----
    ISSUE(0, 0);
    asm volatile("cp.async.commit_group;" ::: "memory");
    ISSUE(32, 1);
    asm volatile("cp.async.commit_group;" ::: "memory");
    ISSUE(64, 2);
    asm volatile("cp.async.commit_group;" ::: "memory");
    asm volatile("cp.async.wait_group 1;" ::: "memory");   // stages 0,1 ready
    __syncthreads();
    LOAD_FA(fa0, dsm, 0);
    LOAD_FB(dsm + B_REG, 0);

    // ---- main loop: 32 chunks, unrolled x4 (constant stage offsets) ----
    for (int cb = 0; cb < 32; cb += 4){
        CHUNK_BODY(cb + 0, 0);
        CHUNK_BODY(cb + 1, 1);
        CHUNK_BODY(cb + 2, 2);
        CHUNK_BODY(cb + 3, 3);
    }

    // ---- epilogue: acc + bias -> y ----
    float bias0[4], bias1[4];
    #pragma unroll
    for (int j = 0; j < 4; j++){
        const int gn = n0 + wn + j * 8 + la3 * 2;
        bias0[j] = __ldg(bc + gn);
        bias1[j] = __ldg(bc + gn + 1);
    }
    #pragma unroll
    for (int i = 0; i < 4; i++){
        const int gm = m0 + wm + i * 16 + lg;
        #pragma unroll
        for (int j = 0; j < 4; j++){
            const int gn = n0 + wn + j * 8 + la3 * 2;
            float2 v0 = make_float2(acc[i][j][0] + bias0[j], acc[i][j][1] + bias1[j]);
            float2 v1 = make_float2(acc[i][j][2] + bias0[j], acc[i][j][3] + bias1[j]);
            *(float2*)(yb + (size_t)gm * ODIM + gn)       = v0;
            *(float2*)(yb + (size_t)(gm + 8) * ODIM + gn) = v1;
        }
    }
}

extern "C" void kernel_launch(void* const* d_in, const int* in_sizes, int n_in,
                              void* d_out, int out_size)
{
    const float* x       = (const float*)d_in[0];
    const int*   cat_ids = (const int*)  d_in[1];
    const float* W       = (const float*)d_in[2];
    const float* bias    = (const float*)d_in[3];
    float*       y       = (float*)d_out;

    cudaFuncSetAttribute(cslin_mma10_kernel,
                         cudaFuncAttributeMaxDynamicSharedMemorySize, SMEM_DYN);
    dim3 grid(1024 / 128, 512 / 256, 64);   // (8, 2, 64)
    cslin_mma10_kernel<<<grid, 512, SMEM_DYN>>>(x, cat_ids, W, bias, y);
}